// round 14
// baseline (speedup 1.0000x reference)
#include <cuda_runtime.h>
#include <cuda_bf16.h>
#include <math.h>

#define Bn 32
#define Tn 384
#define Dn 768
#define D3 2304
#define NB 96
#define GRP_NB 48
#define THRESH 0.95f

__device__ float g_xp[(size_t)Bn * Tn * D3];
__device__ float g_states[(size_t)Bn * Tn * Dn];
__device__ float g_probs[Bn * Tn];
__device__ float g_weights[Bn * Tn];
__device__ int   g_segend[Bn * Tn];
__device__ int   g_nsegs[Bn];
__device__ volatile int g_flag[NB];
__device__ int   g_done;

// h exchange as bf16 hi/lo planes in m16n8k16 A-frag layout:
// [grp][par][48 k16-tiles][32 lanes][4 words][2 halves] (ushort)
__device__ unsigned short g_hH[2][2][48 * 32 * 8];
__device__ unsigned short g_hL[2][2][48 * 32 * 8];
// w_hh bf16 hi/lo B-frags per 16-col slice: [cidx 48][ks 8][q 6][nt 6][lane 32] uint4
#define WFU4 (8 * 6 * 6 * 32)
__device__ uint4 g_wfragU[(size_t)GRP_NB * WFU4];

// xp GEMM operands pre-permuted into bf16 mma-fragment order:
// A: [m-tile 768][kt 48][plane hi/lo][lane 32][4 words]
// B: [n-tile 288][kt 48][lane 32][4 words: b0h, b1h, b0l, b1l]
__device__ unsigned g_fA[(size_t)768 * 48 * 2 * 32 * 4];
__device__ unsigned g_fB[(size_t)288 * 48 * 32 * 4];

__device__ __forceinline__ void bsplit(float2 p, unsigned& hi, unsigned& lo) {
    __nv_bfloat16 hx = __float2bfloat16(p.x);
    __nv_bfloat16 hy = __float2bfloat16(p.y);
    __nv_bfloat162 h; h.x = hx; h.y = hy;
    float lx = p.x - __bfloat162float(hx);
    float ly = p.y - __bfloat162float(hy);
    __nv_bfloat162 l = __floats2bfloat162_rn(lx, ly);
    hi = *(unsigned*)&h; lo = *(unsigned*)&l;
}

// ============ prep A: gather emb[sent] -> frag-ordered planes (hi, lo)
__global__ __launch_bounds__(256) void k_prep_a(const int* __restrict__ sent,
                                                const float* __restrict__ emb) {
    int idx = blockIdx.x * 256 + threadIdx.x;   // over 768*48*32
    int lane = idx & 31;
    int kt = (idx >> 5) % 48;
    int tm = idx / (48 * 32);
    int k0 = kt * 16 + (lane & 3) * 2;
    int m0 = tm * 16 + (lane >> 2);
    const float* x0 = emb + (size_t)sent[m0] * Dn;
    const float* x1 = emb + (size_t)sent[m0 + 8] * Dn;
    float2 p00 = *(const float2*)(x0 + k0);
    float2 p10 = *(const float2*)(x1 + k0);
    float2 p01 = *(const float2*)(x0 + k0 + 8);
    float2 p11 = *(const float2*)(x1 + k0 + 8);
    unsigned* dh = g_fA + (size_t)(tm * 48 + kt) * 256 + lane * 4;  // hi plane
    unsigned* dl = dh + 128;                                        // lo plane
    unsigned h, l;
    bsplit(p00, h, l); dh[0] = h; dl[0] = l;
    bsplit(p10, h, l); dh[1] = h; dl[1] = l;
    bsplit(p01, h, l); dh[2] = h; dl[2] = l;
    bsplit(p11, h, l); dh[3] = h; dl[3] = l;
}

// ============ prep B: w_ih -> frag-ordered hi/lo
__global__ __launch_bounds__(256) void k_prep_b(const float* __restrict__ w_ih) {
    int idx = blockIdx.x * 256 + threadIdx.x;   // over 288*48*32
    int lane = idx & 31;
    int kt = (idx >> 5) % 48;
    int tn = idx / (48 * 32);
    int n = tn * 8 + (lane >> 2);
    int k0 = kt * 16 + (lane & 3) * 2;
    const float* wr = w_ih + (size_t)n * Dn;
    float2 p0 = *(const float2*)(wr + k0);
    float2 p1 = *(const float2*)(wr + k0 + 8);
    unsigned* dst = g_fB + (size_t)idx * 4;
    unsigned h, l;
    bsplit(p0, h, l); dst[0] = h; dst[2] = l;
    bsplit(p1, h, l); dst[1] = h; dst[3] = l;
}

// ============ prep: w_hh -> bf16 hi/lo B-frag layout (per 16-col slice)
__global__ __launch_bounds__(256) void k_prep_w(const float* __restrict__ w_hh) {
    int cidx = blockIdx.x;
    int c0 = cidx * 16;
    for (int it = 0; it < WFU4 / 256; it++) {   // 36
        int idx = it * 256 + threadIdx.x;
        int lane = idx & 31;
        int f = idx >> 5;
        int nt = f % 6;
        int q = (f / 6) % 6;
        int ks = f / 36;
        int gid = lane >> 2, tig = lane & 3;
        int k0 = (ks * 6 + q) * 16 + 2 * tig;
        int nl = nt * 8 + gid;
        int gr = (nl >> 4) * Dn + c0 + (nl & 15);
        const float* wr = w_hh + (size_t)gr * Dn;
        float2 p0 = *(const float2*)(wr + k0);
        float2 p1 = *(const float2*)(wr + k0 + 8);
        unsigned h0, l0, h1, l1;
        bsplit(p0, h0, l0);
        bsplit(p1, h1, l1);
        g_wfragU[(size_t)cidx * WFU4 + idx] = make_uint4(h0, h1, l0, l1);
    }
}

// ============ Kernel 1: xp mma (R13 version — frag GMEM + coalesced SMEM staging)
__device__ __forceinline__ void mma_bf16(float* c, const unsigned* a, const unsigned* b) {
    asm volatile(
        "mma.sync.aligned.m16n8k16.row.col.f32.bf16.bf16.f32 "
        "{%0,%1,%2,%3}, {%4,%5,%6,%7}, {%8,%9}, {%0,%1,%2,%3};"
        : "+f"(c[0]), "+f"(c[1]), "+f"(c[2]), "+f"(c[3])
        : "r"(a[0]), "r"(a[1]), "r"(a[2]), "r"(a[3]), "r"(b[0]), "r"(b[1]));
}

__global__ __launch_bounds__(256, 1) void k_xp_mma(const float* __restrict__ b_ih) {
    __shared__ uint4 sA[2][512];
    __shared__ uint4 sB[2][512];

    const int tid = threadIdx.x;
    const int bm = blockIdx.y * 128;
    const int bn = blockIdx.x * 128;
    const int warp = tid >> 5;
    const int lane = tid & 31;
    const int wm = warp >> 2;
    const int wn = warp & 3;
    const int gid = lane >> 2;
    const int tig = lane & 3;

    const uint4* aptr = (const uint4*)g_fA;
    const uint4* bptr = (const uint4*)g_fB;

    float acc[4][4][4];
#pragma unroll
    for (int i = 0; i < 4; i++)
#pragma unroll
        for (int j = 0; j < 4; j++)
#pragma unroll
            for (int r = 0; r < 4; r++) acc[i][j][r] = 0.f;

#pragma unroll
    for (int k = 0; k < 4; k++) {
        int e = tid + k * 256;
        if (e < 512) {
            int i = e >> 6, off = e & 63;
            sA[0][e] = aptr[((size_t)(blockIdx.y * 8 + i) * 48 + 0) * 64 + off];
        } else {
            int e2 = e - 512, j = e2 >> 5, off = e2 & 31;
            sB[0][e2] = bptr[((size_t)(blockIdx.x * 16 + j) * 48 + 0) * 32 + off];
        }
    }

    for (int kt = 0; kt < 48; kt++) {
        const int cb = kt & 1;
        uint4 pr[4];
        if (kt + 1 < 48) {
#pragma unroll
            for (int k = 0; k < 4; k++) {
                int e = tid + k * 256;
                if (e < 512) {
                    int i = e >> 6, off = e & 63;
                    pr[k] = aptr[((size_t)(blockIdx.y * 8 + i) * 48 + kt + 1) * 64 + off];
                } else {
                    int e2 = e - 512, j = e2 >> 5, off = e2 & 31;
                    pr[k] = bptr[((size_t)(blockIdx.x * 16 + j) * 48 + kt + 1) * 32 + off];
                }
            }
        }
        __syncthreads();

        unsigned Ah[4][4], Al[4][4], Bf[4][4];
#pragma unroll
        for (int i = 0; i < 4; i++) {
            *(uint4*)Ah[i] = sA[cb][(wm * 4 + i) * 64 + lane];
            *(uint4*)Al[i] = sA[cb][(wm * 4 + i) * 64 + 32 + lane];
            *(uint4*)Bf[i] = sB[cb][(wn * 4 + i) * 32 + lane];
        }
#pragma unroll
        for (int i = 0; i < 4; i++)
#pragma unroll
            for (int j = 0; j < 4; j++) {
                mma_bf16(acc[i][j], Ah[i], &Bf[j][0]);
                mma_bf16(acc[i][j], Al[i], &Bf[j][0]);
                mma_bf16(acc[i][j], Ah[i], &Bf[j][2]);
            }

        if (kt + 1 < 48) {
            const int nb = cb ^ 1;
#pragma unroll
            for (int k = 0; k < 4; k++) {
                int e = tid + k * 256;
                if (e < 512) sA[nb][e] = pr[k];
                else sB[nb][e - 512] = pr[k];
            }
        }
    }

#pragma unroll
    for (int j = 0; j < 4; j++) {
        int ncol = bn + (wn * 4 + j) * 8 + 2 * tig;
        float2 bias = *(const float2*)&b_ih[ncol];
#pragma unroll
        for (int i = 0; i < 4; i++) {
            int m0 = bm + (wm * 4 + i) * 16 + gid;
            float2 v0 = {acc[i][j][0] + bias.x, acc[i][j][1] + bias.y};
            float2 v1 = {acc[i][j][2] + bias.x, acc[i][j][3] + bias.y};
            *(float2*)(g_xp + (size_t)m0 * D3 + ncol) = v0;
            *(float2*)(g_xp + (size_t)(m0 + 8) * D3 + ncol) = v1;
        }
    }
}

// ============ Kernel 2: GRU — bf16-split m16n8k16 3-term (108 mma/step/warp)
#define SM_PARTG (8 * 48 * 17)
#define SMEM_GRU (WFU4 * 16 + SM_PARTG * 4)

__global__ __launch_bounds__(256, 1) void k_gru(const float* __restrict__ b_hh) {
    extern __shared__ float sm[];
    uint4* wf = (uint4*)sm;               // [ks][q][nt][lane] uint4
    float* part = sm + WFU4 * 4;          // [ks][48][17]

    const int tid = threadIdx.x;
    const int bid = blockIdx.x;
    const int grp = bid / GRP_NB;
    const int cidx = bid - grp * GRP_NB;
    const int c0 = cidx * 16;
    const int b0 = grp * 16;

    {
        const uint4* src = g_wfragU + (size_t)cidx * WFU4;
        for (int i = tid; i < WFU4; i += 256) wf[i] = src[i];
    }

    const int lane = tid & 31;
    const int ks = tid >> 5;

    // gate identity: 16 cols x 16 batches
    const int gc = tid >> 4;
    const int gb = tid & 15;
    const float br = b_hh[c0 + gc];
    const float bz = b_hh[Dn + c0 + gc];
    const float bnn = b_hh[2 * Dn + c0 + gc];
    // h element position in bf16 A-frag layout
    const int c = c0 + gc;                 // abs col = k index
    const int K16 = c >> 4, kin = c & 15;
    const int flane = (gb & 7) * 4 + ((kin >> 1) & 3);
    const int fword = (gb >> 3) + 2 * (kin >> 3);
    const int gw16 = ((K16 * 32 + flane) * 4 + fword) * 2 + (kin & 1);
    float hold = 0.f;

    g_hH[grp][0][gw16] = 0;
    g_hL[grp][0][gw16] = 0;
    __syncthreads();
    if (tid == 0) { __threadfence(); g_flag[bid] = 1; }
    if (tid < GRP_NB) { while (g_flag[grp * GRP_NB + tid] < 1) {} }
    __threadfence();
    __syncthreads();

    for (int t = 0; t < Tn; t++) {
        const int par = t & 1;

        size_t mrow = (size_t)((b0 + gb) * Tn + t) * D3 + c0 + gc;
        float xr = g_xp[mrow];
        float xz = g_xp[mrow + Dn];
        float xn = g_xp[mrow + 2 * Dn];

        const uint4* hH = (const uint4*)g_hH[grp][par];
        const uint4* hL = (const uint4*)g_hL[grp][par];

        // batch-issue all 12 frag loads (MLP 12)
        uint4 fH[6], fL[6];
#pragma unroll
        for (int q = 0; q < 6; q++) {
            fH[q] = __ldcv(hH + (ks * 6 + q) * 32 + lane);
            fL[q] = __ldcv(hL + (ks * 6 + q) * 32 + lane);
        }

        float acc[6][4];
#pragma unroll
        for (int nt = 0; nt < 6; nt++)
#pragma unroll
            for (int r = 0; r < 4; r++) acc[nt][r] = 0.f;

#pragma unroll
        for (int q = 0; q < 6; q++) {
#pragma unroll
            for (int nt = 0; nt < 6; nt++) {
                uint4 wv = wf[((ks * 6 + q) * 6 + nt) * 32 + lane];
                mma_bf16(acc[nt], (const unsigned*)&fH[q], &wv.x);   // Ah*Bh
                mma_bf16(acc[nt], (const unsigned*)&fL[q], &wv.x);   // Al*Bh
                mma_bf16(acc[nt], (const unsigned*)&fH[q], &wv.z);   // Ah*Bl
            }
        }

        // C scatter: n = nt*8 + 2*(lane&3) + (r&1), batch = (lane>>2) + 8*(r>>1)
#pragma unroll
        for (int nt = 0; nt < 6; nt++)
#pragma unroll
            for (int r = 0; r < 4; r++)
                part[ks * (48 * 17) + (nt * 8 + (lane & 3) * 2 + (r & 1)) * 17 +
                     (lane >> 2) + 8 * (r >> 1)] = acc[nt][r];
        __syncthreads();

        {
            float hr = br, hz = bz, hn = bnn;
#pragma unroll
            for (int s2 = 0; s2 < 8; s2++) {
                const float* pp = part + s2 * (48 * 17);
                hr += pp[gc * 17 + gb];
                hz += pp[(16 + gc) * 17 + gb];
                hn += pp[(32 + gc) * 17 + gb];
            }
            float r = 1.f / (1.f + expf(-(xr + hr)));
            float z = 1.f / (1.f + expf(-(xz + hz)));
            float n = tanhf(xn + r * hn);
            float hnew = (1.f - z) * n + z * hold;
            hold = hnew;
            __nv_bfloat16 bh = __float2bfloat16(hnew);
            float rem = hnew - __bfloat162float(bh);
            __nv_bfloat16 blo = __float2bfloat16(rem);
            g_hH[grp][par ^ 1][gw16] = *(unsigned short*)&bh;
            g_hL[grp][par ^ 1][gw16] = *(unsigned short*)&blo;
            g_states[(size_t)((b0 + gb) * Tn + t) * Dn + c0 + gc] = hnew;
        }

        __syncthreads();
        if (tid == 0) { __threadfence(); g_flag[bid] = t + 2; }
        if (tid < GRP_NB) { while (g_flag[grp * GRP_NB + tid] < t + 2) {} }
        __threadfence();
        __syncthreads();
    }

    if (tid == 0) {
        int old = atomicAdd(&g_done, 1);
        if (old == NB - 1) {
            for (int i = 0; i < NB; i++) g_flag[i] = 0;
            __threadfence();
            g_done = 0;
        }
    }
}

// ============ Kernel 3: probs
__global__ __launch_bounds__(256) void k_probs(const float* __restrict__ w_act,
                                               const float* __restrict__ b_act,
                                               float* __restrict__ out_probs) {
    int warp = threadIdx.x >> 5, lane = threadIdx.x & 31;
    int m = blockIdx.x * 8 + warp;
    const float4* row = (const float4*)(g_states + (size_t)m * Dn);
    const float4* wv = (const float4*)w_act;
    float acc = 0.f;
    for (int i = lane; i < 192; i += 32) {
        float4 v = row[i], w = wv[i];
        acc += v.x * w.x + v.y * w.y + v.z * w.z + v.w * w.w;
    }
#pragma unroll
    for (int off = 16; off; off >>= 1) acc += __shfl_down_sync(0xffffffffu, acc, off);
    if (lane == 0) {
        float p = 1.f / (1.f + expf(-(acc + b_act[0])));
        g_probs[m] = p;
        out_probs[m] = p;
    }
}

// ============ Kernel 4: ACT halting scan
__global__ void k_halt() {
    extern __shared__ float ps[];
    int tid = threadIdx.x;
    for (int i = tid; i < Bn * Tn; i += 384) {
        int b = i / Tn, t = i - b * Tn;
        ps[b * (Tn + 1) + t] = g_probs[i];
    }
    __syncthreads();
    if (tid < Bn) {
        int b = tid;
        const float* pb = ps + b * (Tn + 1);
        float acc = 0.f;
        int ns = 0;
        for (int t = 0; t < Tn; t++) {
            float p = pb[t];
            float a = acc + p;
            if (a > THRESH) {
                g_weights[b * Tn + t] = p - (a - 1.f);
                g_segend[b * Tn + ns] = t;
                ns++;
                acc = 0.f;
            } else {
                g_weights[b * Tn + t] = p;
                acc = a;
            }
        }
        g_nsegs[b] = ns;
    }
}

// ============ Kernel 5: segment sums -> output embs
__global__ __launch_bounds__(128) void k_out(float* __restrict__ out) {
    int bs = blockIdx.x;
    int b = bs / Tn, s = bs - b * Tn;
    float* o = out + (size_t)bs * Dn;
    int tid = threadIdx.x;
    if (s >= g_nsegs[b]) {
        for (int d = tid; d < Dn; d += 128) o[d] = 0.f;
        return;
    }
    int t1 = g_segend[b * Tn + s];
    int t0 = (s == 0) ? 0 : g_segend[b * Tn + s - 1] + 1;
    for (int d = tid; d < Dn; d += 128) {
        float sum = 0.f;
        for (int t = t0; t <= t1; t++)
            sum += g_states[(size_t)(b * Tn + t) * Dn + d] * g_weights[b * Tn + t];
        o[d] = sum;
    }
}

extern "C" void kernel_launch(void* const* d_in, const int* in_sizes, int n_in,
                              void* d_out, int out_size) {
    const int* sent    = (const int*)d_in[0];
    const float* emb   = (const float*)d_in[1];
    const float* w_ih  = (const float*)d_in[2];
    const float* w_hh  = (const float*)d_in[3];
    const float* b_ih  = (const float*)d_in[4];
    const float* b_hh  = (const float*)d_in[5];
    const float* w_act = (const float*)d_in[6];
    const float* b_act = (const float*)d_in[7];
    float* out = (float*)d_out;

    cudaFuncSetAttribute(k_gru, cudaFuncAttributeMaxDynamicSharedMemorySize, SMEM_GRU);
    cudaFuncSetAttribute(k_halt, cudaFuncAttributeMaxDynamicSharedMemorySize,
                         Bn * (Tn + 1) * 4);

    k_prep_a<<<(768 * 48 * 32) / 256, 256>>>(sent, emb);
    k_prep_b<<<(288 * 48 * 32) / 256, 256>>>(w_ih);
    k_prep_w<<<GRP_NB, 256>>>(w_hh);
    k_xp_mma<<<dim3(D3 / 128, (Bn * Tn) / 128), 256>>>(b_ih);
    k_gru<<<NB, 256, SMEM_GRU>>>(b_hh);
    k_probs<<<(Bn * Tn) / 8, 256>>>(w_act, b_act, out + (size_t)Bn * Tn * Dn);
    k_halt<<<1, 384, Bn * (Tn + 1) * 4>>>();
    k_out<<<Bn * Tn, 128>>>(out);
}

// round 15
// speedup vs baseline: 1.2527x; 1.2527x over previous
#include <cuda_runtime.h>
#include <cuda_bf16.h>
#include <math.h>

#define Bn 32
#define Tn 384
#define Dn 768
#define D3 2304
#define NB 96
#define GRP_NB 48
#define THRESH 0.95f

__device__ float g_xp[(size_t)Bn * Tn * D3];
__device__ float g_states[(size_t)Bn * Tn * Dn];
__device__ float g_probs[Bn * Tn];
__device__ float g_weights[Bn * Tn];
__device__ int   g_segend[Bn * Tn];
__device__ int   g_nsegs[Bn];
__device__ volatile int g_flag[NB];
__device__ int   g_done;

// h exchange as bf16 hi/lo planes in m16n8k16 A-frag layout:
// [grp][par][48 k16-tiles][32 lanes][4 words][2 halves] (ushort)
__device__ unsigned short g_hH[2][2][48 * 32 * 8];
__device__ unsigned short g_hL[2][2][48 * 32 * 8];
// w_hh bf16 hi/lo B-frags per 16-col slice: [cidx 48][ks 8][q 6][nt 6][lane 32] uint4
#define WFU4 (8 * 6 * 6 * 32)
__device__ uint4 g_wfragU[(size_t)GRP_NB * WFU4];

// xp GEMM operands pre-permuted into bf16 mma-fragment order:
// A: [m-tile 768][kt 48][plane hi/lo][lane 32][4 words]
// B: [n-tile 288][kt 48][lane 32][4 words: b0h, b1h, b0l, b1l]
__device__ unsigned g_fA[(size_t)768 * 48 * 2 * 32 * 4];
__device__ unsigned g_fB[(size_t)288 * 48 * 32 * 4];

__device__ __forceinline__ void bsplit(float2 p, unsigned& hi, unsigned& lo) {
    __nv_bfloat16 hx = __float2bfloat16(p.x);
    __nv_bfloat16 hy = __float2bfloat16(p.y);
    __nv_bfloat162 h; h.x = hx; h.y = hy;
    float lx = p.x - __bfloat162float(hx);
    float ly = p.y - __bfloat162float(hy);
    __nv_bfloat162 l = __floats2bfloat162_rn(lx, ly);
    hi = *(unsigned*)&h; lo = *(unsigned*)&l;
}

// ============ prep A: gather emb[sent] -> frag-ordered planes (hi, lo)
__global__ __launch_bounds__(256) void k_prep_a(const int* __restrict__ sent,
                                                const float* __restrict__ emb) {
    int idx = blockIdx.x * 256 + threadIdx.x;   // over 768*48*32
    int lane = idx & 31;
    int kt = (idx >> 5) % 48;
    int tm = idx / (48 * 32);
    int k0 = kt * 16 + (lane & 3) * 2;
    int m0 = tm * 16 + (lane >> 2);
    const float* x0 = emb + (size_t)sent[m0] * Dn;
    const float* x1 = emb + (size_t)sent[m0 + 8] * Dn;
    float2 p00 = *(const float2*)(x0 + k0);
    float2 p10 = *(const float2*)(x1 + k0);
    float2 p01 = *(const float2*)(x0 + k0 + 8);
    float2 p11 = *(const float2*)(x1 + k0 + 8);
    unsigned* dh = g_fA + (size_t)(tm * 48 + kt) * 256 + lane * 4;  // hi plane
    unsigned* dl = dh + 128;                                        // lo plane
    unsigned h, l;
    bsplit(p00, h, l); dh[0] = h; dl[0] = l;
    bsplit(p10, h, l); dh[1] = h; dl[1] = l;
    bsplit(p01, h, l); dh[2] = h; dl[2] = l;
    bsplit(p11, h, l); dh[3] = h; dl[3] = l;
}

// ============ prep B: w_ih -> frag-ordered hi/lo
__global__ __launch_bounds__(256) void k_prep_b(const float* __restrict__ w_ih) {
    int idx = blockIdx.x * 256 + threadIdx.x;   // over 288*48*32
    int lane = idx & 31;
    int kt = (idx >> 5) % 48;
    int tn = idx / (48 * 32);
    int n = tn * 8 + (lane >> 2);
    int k0 = kt * 16 + (lane & 3) * 2;
    const float* wr = w_ih + (size_t)n * Dn;
    float2 p0 = *(const float2*)(wr + k0);
    float2 p1 = *(const float2*)(wr + k0 + 8);
    unsigned* dst = g_fB + (size_t)idx * 4;
    unsigned h, l;
    bsplit(p0, h, l); dst[0] = h; dst[2] = l;
    bsplit(p1, h, l); dst[1] = h; dst[3] = l;
}

// ============ prep: w_hh -> bf16 hi/lo B-frag layout (per 16-col slice)
__global__ __launch_bounds__(256) void k_prep_w(const float* __restrict__ w_hh) {
    int cidx = blockIdx.x;
    int c0 = cidx * 16;
    for (int it = 0; it < WFU4 / 256; it++) {   // 36
        int idx = it * 256 + threadIdx.x;
        int lane = idx & 31;
        int f = idx >> 5;
        int nt = f % 6;
        int q = (f / 6) % 6;
        int ks = f / 36;
        int gid = lane >> 2, tig = lane & 3;
        int k0 = (ks * 6 + q) * 16 + 2 * tig;
        int nl = nt * 8 + gid;
        int gr = (nl >> 4) * Dn + c0 + (nl & 15);
        const float* wr = w_hh + (size_t)gr * Dn;
        float2 p0 = *(const float2*)(wr + k0);
        float2 p1 = *(const float2*)(wr + k0 + 8);
        unsigned h0, l0, h1, l1;
        bsplit(p0, h0, l0);
        bsplit(p1, h1, l1);
        g_wfragU[(size_t)cidx * WFU4 + idx] = make_uint4(h0, h1, l0, l1);
    }
}

// ============ Kernel 1: xp mma — frag GMEM + coalesced SMEM staging, 2 blocks/SM
__device__ __forceinline__ void mma_bf16(float* c, const unsigned* a, const unsigned* b) {
    asm volatile(
        "mma.sync.aligned.m16n8k16.row.col.f32.bf16.bf16.f32 "
        "{%0,%1,%2,%3}, {%4,%5,%6,%7}, {%8,%9}, {%0,%1,%2,%3};"
        : "+f"(c[0]), "+f"(c[1]), "+f"(c[2]), "+f"(c[3])
        : "r"(a[0]), "r"(a[1]), "r"(a[2]), "r"(a[3]), "r"(b[0]), "r"(b[1]));
}

__global__ __launch_bounds__(256, 2) void k_xp_mma(const float* __restrict__ b_ih) {
    __shared__ uint4 sA[2][512];
    __shared__ uint4 sB[2][512];

    const int tid = threadIdx.x;
    const int bm = blockIdx.y * 128;
    const int bn = blockIdx.x * 128;
    const int warp = tid >> 5;
    const int lane = tid & 31;
    const int wm = warp >> 2;
    const int wn = warp & 3;
    const int gid = lane >> 2;
    const int tig = lane & 3;

    const uint4* aptr = (const uint4*)g_fA;
    const uint4* bptr = (const uint4*)g_fB;

    float acc[4][4][4];
#pragma unroll
    for (int i = 0; i < 4; i++)
#pragma unroll
        for (int j = 0; j < 4; j++)
#pragma unroll
            for (int r = 0; r < 4; r++) acc[i][j][r] = 0.f;

#pragma unroll
    for (int k = 0; k < 4; k++) {
        int e = tid + k * 256;
        if (e < 512) {
            int i = e >> 6, off = e & 63;
            sA[0][e] = aptr[((size_t)(blockIdx.y * 8 + i) * 48 + 0) * 64 + off];
        } else {
            int e2 = e - 512, j = e2 >> 5, off = e2 & 31;
            sB[0][e2] = bptr[((size_t)(blockIdx.x * 16 + j) * 48 + 0) * 32 + off];
        }
    }

    for (int kt = 0; kt < 48; kt++) {
        const int cb = kt & 1;
        uint4 pr[4];
        if (kt + 1 < 48) {
#pragma unroll
            for (int k = 0; k < 4; k++) {
                int e = tid + k * 256;
                if (e < 512) {
                    int i = e >> 6, off = e & 63;
                    pr[k] = aptr[((size_t)(blockIdx.y * 8 + i) * 48 + kt + 1) * 64 + off];
                } else {
                    int e2 = e - 512, j = e2 >> 5, off = e2 & 31;
                    pr[k] = bptr[((size_t)(blockIdx.x * 16 + j) * 48 + kt + 1) * 32 + off];
                }
            }
        }
        __syncthreads();

        unsigned Ah[4][4], Al[4][4], Bf[4][4];
#pragma unroll
        for (int i = 0; i < 4; i++) {
            *(uint4*)Ah[i] = sA[cb][(wm * 4 + i) * 64 + lane];
            *(uint4*)Al[i] = sA[cb][(wm * 4 + i) * 64 + 32 + lane];
            *(uint4*)Bf[i] = sB[cb][(wn * 4 + i) * 32 + lane];
        }
#pragma unroll
        for (int i = 0; i < 4; i++)
#pragma unroll
            for (int j = 0; j < 4; j++) {
                mma_bf16(acc[i][j], Ah[i], &Bf[j][0]);
                mma_bf16(acc[i][j], Al[i], &Bf[j][0]);
                mma_bf16(acc[i][j], Ah[i], &Bf[j][2]);
            }

        if (kt + 1 < 48) {
            const int nb = cb ^ 1;
#pragma unroll
            for (int k = 0; k < 4; k++) {
                int e = tid + k * 256;
                if (e < 512) sA[nb][e] = pr[k];
                else sB[nb][e - 512] = pr[k];
            }
        }
    }

#pragma unroll
    for (int j = 0; j < 4; j++) {
        int ncol = bn + (wn * 4 + j) * 8 + 2 * tig;
        float2 bias = *(const float2*)&b_ih[ncol];
#pragma unroll
        for (int i = 0; i < 4; i++) {
            int m0 = bm + (wm * 4 + i) * 16 + gid;
            float2 v0 = {acc[i][j][0] + bias.x, acc[i][j][1] + bias.y};
            float2 v1 = {acc[i][j][2] + bias.x, acc[i][j][3] + bias.y};
            *(float2*)(g_xp + (size_t)m0 * D3 + ncol) = v0;
            *(float2*)(g_xp + (size_t)(m0 + 8) * D3 + ncol) = v1;
        }
    }
}

// ============ Kernel 2: GRU — bf16-split m16n8k16 3-term (108 mma/step/warp)
#define SM_PARTG (8 * 48 * 17)
#define SMEM_GRU (WFU4 * 16 + SM_PARTG * 4)

__global__ __launch_bounds__(256, 1) void k_gru(const float* __restrict__ b_hh) {
    extern __shared__ float sm[];
    uint4* wf = (uint4*)sm;               // [ks][q][nt][lane] uint4
    float* part = sm + WFU4 * 4;          // [ks][48][17]

    const int tid = threadIdx.x;
    const int bid = blockIdx.x;
    const int grp = bid / GRP_NB;
    const int cidx = bid - grp * GRP_NB;
    const int c0 = cidx * 16;
    const int b0 = grp * 16;

    {
        const uint4* src = g_wfragU + (size_t)cidx * WFU4;
        for (int i = tid; i < WFU4; i += 256) wf[i] = src[i];
    }

    const int lane = tid & 31;
    const int ks = tid >> 5;

    const int gc = tid >> 4;
    const int gb = tid & 15;
    const float br = b_hh[c0 + gc];
    const float bz = b_hh[Dn + c0 + gc];
    const float bnn = b_hh[2 * Dn + c0 + gc];
    const int c = c0 + gc;
    const int K16 = c >> 4, kin = c & 15;
    const int flane = (gb & 7) * 4 + ((kin >> 1) & 3);
    const int fword = (gb >> 3) + 2 * (kin >> 3);
    const int gw16 = ((K16 * 32 + flane) * 4 + fword) * 2 + (kin & 1);
    float hold = 0.f;

    g_hH[grp][0][gw16] = 0;
    g_hL[grp][0][gw16] = 0;
    __syncthreads();
    if (tid == 0) { __threadfence(); g_flag[bid] = 1; }
    if (tid < GRP_NB) { while (g_flag[grp * GRP_NB + tid] < 1) {} }
    __threadfence();
    __syncthreads();

    for (int t = 0; t < Tn; t++) {
        const int par = t & 1;

        size_t mrow = (size_t)((b0 + gb) * Tn + t) * D3 + c0 + gc;
        float xr = g_xp[mrow];
        float xz = g_xp[mrow + Dn];
        float xn = g_xp[mrow + 2 * Dn];

        const uint4* hH = (const uint4*)g_hH[grp][par];
        const uint4* hL = (const uint4*)g_hL[grp][par];

        uint4 fH[6], fL[6];
#pragma unroll
        for (int q = 0; q < 6; q++) {
            fH[q] = __ldcv(hH + (ks * 6 + q) * 32 + lane);
            fL[q] = __ldcv(hL + (ks * 6 + q) * 32 + lane);
        }

        float acc[6][4];
#pragma unroll
        for (int nt = 0; nt < 6; nt++)
#pragma unroll
            for (int r = 0; r < 4; r++) acc[nt][r] = 0.f;

#pragma unroll
        for (int q = 0; q < 6; q++) {
#pragma unroll
            for (int nt = 0; nt < 6; nt++) {
                uint4 wv = wf[((ks * 6 + q) * 6 + nt) * 32 + lane];
                mma_bf16(acc[nt], (const unsigned*)&fH[q], &wv.x);   // Ah*Bh
                mma_bf16(acc[nt], (const unsigned*)&fL[q], &wv.x);   // Al*Bh
                mma_bf16(acc[nt], (const unsigned*)&fH[q], &wv.z);   // Ah*Bl
            }
        }

#pragma unroll
        for (int nt = 0; nt < 6; nt++)
#pragma unroll
            for (int r = 0; r < 4; r++)
                part[ks * (48 * 17) + (nt * 8 + (lane & 3) * 2 + (r & 1)) * 17 +
                     (lane >> 2) + 8 * (r >> 1)] = acc[nt][r];
        __syncthreads();

        {
            float hr = br, hz = bz, hn = bnn;
#pragma unroll
            for (int s2 = 0; s2 < 8; s2++) {
                const float* pp = part + s2 * (48 * 17);
                hr += pp[gc * 17 + gb];
                hz += pp[(16 + gc) * 17 + gb];
                hn += pp[(32 + gc) * 17 + gb];
            }
            float r = 1.f / (1.f + expf(-(xr + hr)));
            float z = 1.f / (1.f + expf(-(xz + hz)));
            float n = tanhf(xn + r * hn);
            float hnew = (1.f - z) * n + z * hold;
            hold = hnew;
            __nv_bfloat16 bh = __float2bfloat16(hnew);
            float rem = hnew - __bfloat162float(bh);
            __nv_bfloat16 blo = __float2bfloat16(rem);
            g_hH[grp][par ^ 1][gw16] = *(unsigned short*)&bh;
            g_hL[grp][par ^ 1][gw16] = *(unsigned short*)&blo;
            g_states[(size_t)((b0 + gb) * Tn + t) * Dn + c0 + gc] = hnew;
        }

        __syncthreads();
        if (tid == 0) { __threadfence(); g_flag[bid] = t + 2; }
        if (tid < GRP_NB) { while (g_flag[grp * GRP_NB + tid] < t + 2) {} }
        __threadfence();
        __syncthreads();
    }

    if (tid == 0) {
        int old = atomicAdd(&g_done, 1);
        if (old == NB - 1) {
            for (int i = 0; i < NB; i++) g_flag[i] = 0;
            __threadfence();
            g_done = 0;
        }
    }
}

// ============ Kernel 3: probs
__global__ __launch_bounds__(256) void k_probs(const float* __restrict__ w_act,
                                               const float* __restrict__ b_act,
                                               float* __restrict__ out_probs) {
    int warp = threadIdx.x >> 5, lane = threadIdx.x & 31;
    int m = blockIdx.x * 8 + warp;
    const float4* row = (const float4*)(g_states + (size_t)m * Dn);
    const float4* wv = (const float4*)w_act;
    float acc = 0.f;
    for (int i = lane; i < 192; i += 32) {
        float4 v = row[i], w = wv[i];
        acc += v.x * w.x + v.y * w.y + v.z * w.z + v.w * w.w;
    }
#pragma unroll
    for (int off = 16; off; off >>= 1) acc += __shfl_down_sync(0xffffffffu, acc, off);
    if (lane == 0) {
        float p = 1.f / (1.f + expf(-(acc + b_act[0])));
        g_probs[m] = p;
        out_probs[m] = p;
    }
}

// ============ Kernel 4: ACT halting scan
__global__ void k_halt() {
    extern __shared__ float ps[];
    int tid = threadIdx.x;
    for (int i = tid; i < Bn * Tn; i += 384) {
        int b = i / Tn, t = i - b * Tn;
        ps[b * (Tn + 1) + t] = g_probs[i];
    }
    __syncthreads();
    if (tid < Bn) {
        int b = tid;
        const float* pb = ps + b * (Tn + 1);
        float acc = 0.f;
        int ns = 0;
        for (int t = 0; t < Tn; t++) {
            float p = pb[t];
            float a = acc + p;
            if (a > THRESH) {
                g_weights[b * Tn + t] = p - (a - 1.f);
                g_segend[b * Tn + ns] = t;
                ns++;
                acc = 0.f;
            } else {
                g_weights[b * Tn + t] = p;
                acc = a;
            }
        }
        g_nsegs[b] = ns;
    }
}

// ============ Kernel 5: segment sums -> output embs
__global__ __launch_bounds__(128) void k_out(float* __restrict__ out) {
    int bs = blockIdx.x;
    int b = bs / Tn, s = bs - b * Tn;
    float* o = out + (size_t)bs * Dn;
    int tid = threadIdx.x;
    if (s >= g_nsegs[b]) {
        for (int d = tid; d < Dn; d += 128) o[d] = 0.f;
        return;
    }
    int t1 = g_segend[b * Tn + s];
    int t0 = (s == 0) ? 0 : g_segend[b * Tn + s - 1] + 1;
    for (int d = tid; d < Dn; d += 128) {
        float sum = 0.f;
        for (int t = t0; t <= t1; t++)
            sum += g_states[(size_t)(b * Tn + t) * Dn + d] * g_weights[b * Tn + t];
        o[d] = sum;
    }
}

extern "C" void kernel_launch(void* const* d_in, const int* in_sizes, int n_in,
                              void* d_out, int out_size) {
    const int* sent    = (const int*)d_in[0];
    const float* emb   = (const float*)d_in[1];
    const float* w_ih  = (const float*)d_in[2];
    const float* w_hh  = (const float*)d_in[3];
    const float* b_ih  = (const float*)d_in[4];
    const float* b_hh  = (const float*)d_in[5];
    const float* w_act = (const float*)d_in[6];
    const float* b_act = (const float*)d_in[7];
    float* out = (float*)d_out;

    cudaFuncSetAttribute(k_gru, cudaFuncAttributeMaxDynamicSharedMemorySize, SMEM_GRU);
    cudaFuncSetAttribute(k_halt, cudaFuncAttributeMaxDynamicSharedMemorySize,
                         Bn * (Tn + 1) * 4);

    k_prep_a<<<(768 * 48 * 32) / 256, 256>>>(sent, emb);
    k_prep_b<<<(288 * 48 * 32) / 256, 256>>>(w_ih);
    k_prep_w<<<GRP_NB, 256>>>(w_hh);
    k_xp_mma<<<dim3(D3 / 128, (Bn * Tn) / 128), 256>>>(b_ih);
    k_gru<<<NB, 256, SMEM_GRU>>>(b_hh);
    k_probs<<<(Bn * Tn) / 8, 256>>>(w_act, b_act, out + (size_t)Bn * Tn * Dn);
    k_halt<<<1, 384, Bn * (Tn + 1) * 4>>>();
    k_out<<<Bn * Tn, 128>>>(out);
}